// round 2
// baseline (speedup 1.0000x reference)
#include <cuda_runtime.h>
#include <math.h>

// ---------------- problem constants ----------------
#define BB 32
#define MM 512
#define DD 512
#define HH 8
#define FF 8
#define CC 64           // DD / FF
#define TDD 4096        // FF * MM
#define MD (MM * DD)    // 262144

// ---------------- device scratch (no allocs allowed) ----------------
__device__ float g_x1 [(size_t)BB * MD];
__device__ float g_q  [(size_t)HH * BB * MD];
__device__ float g_k  [(size_t)HH * BB * MD];
__device__ float g_v  [(size_t)HH * BB * MD];
__device__ float g_s  [(size_t)HH * BB * MM * MM];
__device__ float g_cat[(size_t)BB * MM * HH * DD];
__device__ float g_x2 [(size_t)BB * MD];
__device__ float g_x3 [(size_t)BB * MD];
__device__ float g_t  [(size_t)BB * CC * TDD];
__device__ float g_tq [(size_t)BB * CC * TDD];
__device__ float g_tk [(size_t)BB * CC * TDD];
__device__ float g_tv [(size_t)BB * CC * TDD];
__device__ float g_s2 [(size_t)BB * CC * CC];
__device__ float g_t2 [(size_t)BB * CC * TDD];
__device__ float g_ff [BB];

// ---------------- RMSNorm (per-batch global norm) ----------------
__global__ void rms_reduce_k(const float* __restrict__ x, float* __restrict__ ff) {
    int b = blockIdx.x;
    const float* xb = x + (size_t)b * MD;
    float s = 0.f;
    for (int i = threadIdx.x; i < MD; i += blockDim.x) {
        float v = xb[i];
        s += v * v;
    }
    __shared__ float sm[32];
    for (int o = 16; o; o >>= 1) s += __shfl_xor_sync(0xffffffffu, s, o);
    if ((threadIdx.x & 31) == 0) sm[threadIdx.x >> 5] = s;
    __syncthreads();
    if (threadIdx.x < 32) {
        s = (threadIdx.x < (blockDim.x >> 5)) ? sm[threadIdx.x] : 0.f;
        for (int o = 16; o; o >>= 1) s += __shfl_xor_sync(0xffffffffu, s, o);
        if (threadIdx.x == 0) ff[b] = sqrtf((float)MD) * rsqrtf(s);
    }
}

__global__ void rms_apply_k(const float* __restrict__ x, const float* __restrict__ scale,
                            const float* __restrict__ ff, float* __restrict__ y) {
    long i = (long)blockIdx.x * blockDim.x + threadIdx.x;
    if (i >= (long)BB * MD) return;
    int b  = (int)(i / MD);
    int md = (int)(i % MD);
    y[i] = x[i] * scale[md] * ff[b];
}

// ---------------- RoPE (in place). rows laid out (..., angmod, 2*halfd) ----------------
// theta_i = 10000^(-2*(i-1)/(2*halfd))  [reference uses (i-1)]
__global__ void rope_k(float* __restrict__ q, long total_pairs, int halfd, int angmod, float thc) {
    long idx = (long)blockIdx.x * blockDim.x + threadIdx.x;
    if (idx >= total_pairs) return;
    int  pair = (int)(idx % halfd);
    long row  = idx / halfd;
    int  a    = (int)(row % angmod);
    float theta = exp2f(thc * ((float)pair - 1.0f));
    float sn, cs;
    sincosf((float)a * theta, &sn, &cs);
    float* p = q + row * (long)(2 * halfd) + 2 * pair;
    float e = p[0], o = p[1];
    p[0] = fmaf(e, cs, o * sn);
    p[1] = fmaf(-e, sn, o * cs);
}

// ---------------- row softmax (warp per row) ----------------
__global__ void softmax_k(float* __restrict__ s, int L, long nrows) {
    long warp = (long)blockIdx.x * (blockDim.x >> 5) + (threadIdx.x >> 5);
    if (warp >= nrows) return;
    int lane = threadIdx.x & 31;
    float* row = s + warp * (long)L;
    float mx = -INFINITY;
    for (int i = lane; i < L; i += 32) mx = fmaxf(mx, row[i]);
    for (int o = 16; o; o >>= 1) mx = fmaxf(mx, __shfl_xor_sync(0xffffffffu, mx, o));
    float sum = 0.f;
    for (int i = lane; i < L; i += 32) {
        float e = __expf(row[i] - mx);
        row[i] = e;
        sum += e;
    }
    for (int o = 16; o; o >>= 1) sum += __shfl_xor_sync(0xffffffffu, sum, o);
    float inv = 1.f / sum;
    for (int i = lane; i < L; i += 32) row[i] *= inv;
}

// ================= big SGEMM: 128x128 tile, BK=16, 8x8 microtile, 256 thr ==========
// C = alpha * A*op(B) (+ R) (+ bias). batch z: zo = z/inner, zi = z%inner.
// Requires M,N multiples of 128, K multiple of 16.
template<bool TRANSB, bool RES, bool BIAS>
__global__ void __launch_bounds__(256) sgemm128_k(
    const float* __restrict__ A, int lda, long sAo, long sAi,
    const float* __restrict__ Bm, int ldb, long sBo, long sBi,
    float*       __restrict__ Cm, int ldc, long sCo, long sCi,
    const float* __restrict__ R, int ldr, long sRi,
    const float* __restrict__ bias,
    int K, int inner, float alpha)
{
    int z  = blockIdx.z;
    int zo = z / inner;
    int zi = z - zo * inner;
    A  += zo * sAo + zi * sAi;
    Bm += zo * sBo + zi * sBi;
    Cm += zo * sCo + zi * sCi;
    if (RES) R += (long)zi * sRi;

    __shared__ __align__(16) float As[16][132];
    __shared__ __align__(16) float Bs[16][132];

    const int tid = threadIdx.x;
    const int m0 = blockIdx.y << 7;
    const int n0 = blockIdx.x << 7;
    const int tx = tid & 15, ty = tid >> 4;

    const int ar = tid >> 2;          // 0..63
    const int ac = (tid & 3) << 2;    // 0,4,8,12
    const int br = tid >> 5;          // 0..7
    const int bc = (tid & 31) << 2;   // 0..124

    float acc[8][8] = {};

    for (int k0 = 0; k0 < K; k0 += 16) {
        #pragma unroll
        for (int g = 0; g < 2; g++) {
            int r = ar + (g << 6);
            float4 av = *reinterpret_cast<const float4*>(&A[(long)(m0 + r) * lda + k0 + ac]);
            As[ac + 0][r] = av.x; As[ac + 1][r] = av.y;
            As[ac + 2][r] = av.z; As[ac + 3][r] = av.w;
        }
        if (!TRANSB) {
            #pragma unroll
            for (int g = 0; g < 2; g++) {
                int r = br + (g << 3);
                float4 bv = *reinterpret_cast<const float4*>(&Bm[(long)(k0 + r) * ldb + n0 + bc]);
                *reinterpret_cast<float4*>(&Bs[r][bc]) = bv;
            }
        } else {
            #pragma unroll
            for (int g = 0; g < 2; g++) {
                int r = ar + (g << 6);   // n index within tile
                float4 bv = *reinterpret_cast<const float4*>(&Bm[(long)(n0 + r) * ldb + k0 + ac]);
                Bs[ac + 0][r] = bv.x; Bs[ac + 1][r] = bv.y;
                Bs[ac + 2][r] = bv.z; Bs[ac + 3][r] = bv.w;
            }
        }
        __syncthreads();
        #pragma unroll
        for (int k = 0; k < 16; k++) {
            float a[8], b[8];
            *reinterpret_cast<float4*>(&a[0]) = *reinterpret_cast<const float4*>(&As[k][ty << 2]);
            *reinterpret_cast<float4*>(&a[4]) = *reinterpret_cast<const float4*>(&As[k][(ty << 2) + 64]);
            *reinterpret_cast<float4*>(&b[0]) = *reinterpret_cast<const float4*>(&Bs[k][tx << 2]);
            *reinterpret_cast<float4*>(&b[4]) = *reinterpret_cast<const float4*>(&Bs[k][(tx << 2) + 64]);
            #pragma unroll
            for (int i = 0; i < 8; i++)
                #pragma unroll
                for (int j = 0; j < 8; j++)
                    acc[i][j] = fmaf(a[i], b[j], acc[i][j]);
        }
        __syncthreads();
    }

    #pragma unroll
    for (int i = 0; i < 8; i++) {
        int m = m0 + (ty << 2) + ((i < 4) ? i : (64 + i - 4));
        #pragma unroll
        for (int j = 0; j < 8; j++) {
            int n = n0 + (tx << 2) + ((j < 4) ? j : (64 + j - 4));
            float vv = acc[i][j] * alpha;
            if (RES)  vv += R[(long)m * ldr + n];
            if (BIAS) vv += bias[n];
            Cm[(long)m * ldc + n] = vv;
        }
    }
}

// ================= small SGEMM: 64x64 tile, BK=16, 4x4 microtile (stage-2 attn) =====
template<bool TRANSB, bool RES, bool BIAS>
__global__ void __launch_bounds__(256) sgemm_k(
    const float* __restrict__ A, int lda, long sAo, long sAi,
    const float* __restrict__ Bm, int ldb, long sBo, long sBi,
    float*       __restrict__ Cm, int ldc, long sCo, long sCi,
    const float* __restrict__ R, int ldr, long sRi,
    const float* __restrict__ bias,
    int K, int inner, float alpha)
{
    int z  = blockIdx.z;
    int zo = z / inner;
    int zi = z - zo * inner;
    A  += zo * sAo + zi * sAi;
    Bm += zo * sBo + zi * sBi;
    Cm += zo * sCo + zi * sCi;
    if (RES) R += (long)zi * sRi;

    __shared__ __align__(16) float As[16][68];
    __shared__ __align__(16) float Bs[16][68];

    const int tid = threadIdx.x;
    const int m0 = blockIdx.y << 6;
    const int n0 = blockIdx.x << 6;
    const int tx = tid & 15, ty = tid >> 4;

    const int ar = tid >> 2;
    const int ac = (tid & 3) << 2;
    const int br = tid >> 4;
    const int bc = (tid & 15) << 2;

    float acc[4][4] = {};

    for (int k0 = 0; k0 < K; k0 += 16) {
        float4 av = *reinterpret_cast<const float4*>(&A[(long)(m0 + ar) * lda + k0 + ac]);
        As[ac + 0][ar] = av.x; As[ac + 1][ar] = av.y;
        As[ac + 2][ar] = av.z; As[ac + 3][ar] = av.w;
        if (!TRANSB) {
            float4 bv = *reinterpret_cast<const float4*>(&Bm[(long)(k0 + br) * ldb + n0 + bc]);
            *reinterpret_cast<float4*>(&Bs[br][bc]) = bv;
        } else {
            float4 bv = *reinterpret_cast<const float4*>(&Bm[(long)(n0 + ar) * ldb + k0 + ac]);
            Bs[ac + 0][ar] = bv.x; Bs[ac + 1][ar] = bv.y;
            Bs[ac + 2][ar] = bv.z; Bs[ac + 3][ar] = bv.w;
        }
        __syncthreads();
        #pragma unroll
        for (int k = 0; k < 16; k++) {
            float4 a4 = *reinterpret_cast<const float4*>(&As[k][ty << 2]);
            float4 b4 = *reinterpret_cast<const float4*>(&Bs[k][tx << 2]);
            float a[4] = {a4.x, a4.y, a4.z, a4.w};
            float b[4] = {b4.x, b4.y, b4.z, b4.w};
            #pragma unroll
            for (int i = 0; i < 4; i++)
                #pragma unroll
                for (int j = 0; j < 4; j++)
                    acc[i][j] = fmaf(a[i], b[j], acc[i][j]);
        }
        __syncthreads();
    }

    #pragma unroll
    for (int i = 0; i < 4; i++) {
        int m = m0 + (ty << 2) + i;
        #pragma unroll
        for (int j = 0; j < 4; j++) {
            int n = n0 + (tx << 2) + j;
            float v = acc[i][j] * alpha;
            if (RES)  v += R[(long)m * ldr + n];
            if (BIAS) v += bias[n];
            Cm[(long)m * ldc + n] = v;
        }
    }
}

// ---------------- layout shuffles ----------------
// t[b][c][p*MM + m] = x3[b][m][c*FF + p]
__global__ void build_t_k(const float* __restrict__ x3, float* __restrict__ t) {
    long i = (long)blockIdx.x * blockDim.x + threadIdx.x;
    if (i >= (long)BB * CC * TDD) return;
    int  j  = (int)(i % TDD);
    long bc = i / TDD;
    int  c  = (int)(bc % CC);
    int  b  = (int)(bc / CC);
    int  p  = j >> 9;
    int  m  = j & 511;
    t[i] = x3[(long)b * MD + (long)m * DD + c * FF + p];
}

// out[b][m][c*FF+p] = t2[b][c][p*MM + m]
__global__ void build_out_k(const float* __restrict__ t2, float* __restrict__ out) {
    long i = (long)blockIdx.x * blockDim.x + threadIdx.x;
    if (i >= (long)BB * MD) return;
    int  d  = (int)(i % DD);
    long bm = i / DD;
    int  m  = (int)(bm % MM);
    int  b  = (int)(bm / MM);
    int  c  = d >> 3;
    int  p  = d & 7;
    out[i] = t2[(long)b * (CC * TDD) + (long)c * TDD + p * MM + m];
}

// ---------------- launch ----------------
extern "C" void kernel_launch(void* const* d_in, const int* in_sizes, int n_in,
                              void* d_out, int out_size) {
    const float* x     = (const float*)d_in[0];
    const float* scale = (const float*)d_in[1];
    const float* wq    = (const float*)d_in[2];
    const float* wk    = (const float*)d_in[3];
    const float* wv    = (const float*)d_in[4];
    const float* lin_w = (const float*)d_in[5];
    const float* lin_b = (const float*)d_in[6];
    const float* twq   = (const float*)d_in[7];
    const float* twk   = (const float*)d_in[8];
    const float* twv   = (const float*)d_in[9];
    float* out = (float*)d_out;

    float *x1, *q, *k, *v, *s, *cat, *x2, *x3, *t, *tq, *tk, *tv, *s2, *t2, *ff;
    cudaGetSymbolAddress((void**)&x1,  g_x1);
    cudaGetSymbolAddress((void**)&q,   g_q);
    cudaGetSymbolAddress((void**)&k,   g_k);
    cudaGetSymbolAddress((void**)&v,   g_v);
    cudaGetSymbolAddress((void**)&s,   g_s);
    cudaGetSymbolAddress((void**)&cat, g_cat);
    cudaGetSymbolAddress((void**)&x2,  g_x2);
    cudaGetSymbolAddress((void**)&x3,  g_x3);
    cudaGetSymbolAddress((void**)&t,   g_t);
    cudaGetSymbolAddress((void**)&tq,  g_tq);
    cudaGetSymbolAddress((void**)&tk,  g_tk);
    cudaGetSymbolAddress((void**)&tv,  g_tv);
    cudaGetSymbolAddress((void**)&s2,  g_s2);
    cudaGetSymbolAddress((void**)&t2,  g_t2);
    cudaGetSymbolAddress((void**)&ff,  g_ff);

    const float th1 = -2.0f * log2f(10000.0f) / (float)DD;
    const float th2 = -2.0f * log2f(10000.0f) / (float)TDD;
    const float al1 = 1.0f / sqrtf((float)DD);
    const float al2 = 1.0f / sqrtf((float)TDD);

    // 1) x1 = rmsnorm(x)
    rms_reduce_k<<<BB, 1024>>>(x, ff);
    rms_apply_k<<<(BB * MD) / 256, 256>>>(x, scale, ff, x1);

    // 2) q/k/v[h,b] = x1[b] @ w[h]   (z = h*BB + b)
    {
        dim3 g(DD / 128, MM / 128, HH * BB);
        sgemm128_k<false,false,false><<<g, 256>>>(x1, DD, 0, MD, wq, DD, (long)MD, 0,
                                                  q, DD, (long)BB * MD, MD,
                                                  nullptr, 0, 0, nullptr, DD, BB, 1.f);
        sgemm128_k<false,false,false><<<g, 256>>>(x1, DD, 0, MD, wk, DD, (long)MD, 0,
                                                  k, DD, (long)BB * MD, MD,
                                                  nullptr, 0, 0, nullptr, DD, BB, 1.f);
        sgemm128_k<false,false,false><<<g, 256>>>(x1, DD, 0, MD, wv, DD, (long)MD, 0,
                                                  v, DD, (long)BB * MD, MD,
                                                  nullptr, 0, 0, nullptr, DD, BB, 1.f);
    }

    // 3) RoPE on q,k
    {
        long tp = (long)HH * BB * MM * (DD / 2);
        int blocks = (int)((tp + 255) / 256);
        rope_k<<<blocks, 256>>>(q, tp, DD / 2, MM, th1);
        rope_k<<<blocks, 256>>>(k, tp, DD / 2, MM, th1);
    }

    // 4) S = (q/sqrt(D)) @ k^T ; softmax ; O = P @ v  (into cat layout)
    {
        dim3 g(MM / 128, MM / 128, HH * BB);
        sgemm128_k<true,false,false><<<g, 256>>>(q, DD, (long)BB * MD, MD,
                                                 k, DD, (long)BB * MD, MD,
                                                 s, MM, (long)BB * MM * MM, (long)MM * MM,
                                                 nullptr, 0, 0, nullptr, DD, BB, al1);
        long nrows = (long)HH * BB * MM;
        softmax_k<<<(int)(nrows / 8), 256>>>(s, MM, nrows);
        dim3 g2(DD / 128, MM / 128, HH * BB);
        sgemm128_k<false,false,false><<<g2, 256>>>(s, MM, (long)BB * MM * MM, (long)MM * MM,
                                                   v, DD, (long)BB * MD, MD,
                                                   cat, HH * DD, (long)DD, (long)MM * HH * DD,
                                                   nullptr, 0, 0, nullptr, MM, BB, 1.f);
    }

    // 5) x2 = x1 + cat @ lin_w + lin_b   (M=16384, N=512, K=4096)
    {
        dim3 g(DD / 128, (BB * MM) / 128, 1);
        sgemm128_k<false,true,true><<<g, 256>>>(cat, HH * DD, 0, 0, lin_w, DD, 0, 0,
                                                x2, DD, 0, 0,
                                                x1, DD, 0, lin_b, HH * DD, 1, 1.f);
    }

    // 6) x3 = rmsnorm(x2)
    rms_reduce_k<<<BB, 1024>>>(x2, ff);
    rms_apply_k<<<(BB * MD) / 256, 256>>>(x2, scale, ff, x3);

    // 7) t  (channel transpose)
    build_t_k<<<(int)(((long)BB * CC * TDD) / 256), 256>>>(x3, t);

    // 8) tq/tk/tv = t @ tw   (M=2048, N=4096, K=4096)
    {
        dim3 g(TDD / 128, (BB * CC) / 128, 1);
        sgemm128_k<false,false,false><<<g, 256>>>(t, TDD, 0, 0, twq, TDD, 0, 0, tq, TDD, 0, 0,
                                                  nullptr, 0, 0, nullptr, TDD, 1, 1.f);
        sgemm128_k<false,false,false><<<g, 256>>>(t, TDD, 0, 0, twk, TDD, 0, 0, tk, TDD, 0, 0,
                                                  nullptr, 0, 0, nullptr, TDD, 1, 1.f);
        sgemm128_k<false,false,false><<<g, 256>>>(t, TDD, 0, 0, twv, TDD, 0, 0, tv, TDD, 0, 0,
                                                  nullptr, 0, 0, nullptr, TDD, 1, 1.f);
    }

    // 9) RoPE on tq,tk
    {
        long tp = (long)BB * CC * (TDD / 2);
        int blocks = (int)((tp + 255) / 256);
        rope_k<<<blocks, 256>>>(tq, tp, TDD / 2, CC, th2);
        rope_k<<<blocks, 256>>>(tk, tp, TDD / 2, CC, th2);
    }

    // 10) S2 = (tq/64) @ tk^T per batch; softmax; t2 = t + P2 @ tv
    {
        dim3 g(1, 1, BB);
        sgemm_k<true,false,false><<<g, 256>>>(tq, TDD, 0, (long)CC * TDD,
                                              tk, TDD, 0, (long)CC * TDD,
                                              s2, CC, 0, (long)CC * CC,
                                              nullptr, 0, 0, nullptr, TDD, BB, al2);
        softmax_k<<<(BB * CC) / 8, 256>>>(s2, CC, (long)BB * CC);
        dim3 g2(TDD / 64, 1, BB);
        sgemm_k<false,true,false><<<g2, 256>>>(s2, CC, 0, (long)CC * CC,
                                               tv, TDD, 0, (long)CC * TDD,
                                               t2, TDD, 0, (long)CC * TDD,
                                               t, TDD, (long)CC * TDD, nullptr,
                                               CC, BB, 1.f);
    }

    // 11) inverse transpose into d_out
    build_out_k<<<(int)(((long)BB * MD) / 256), 256>>>(t2, out);
}

// round 3
// speedup vs baseline: 1.6657x; 1.6657x over previous
#include <cuda_runtime.h>
#include <math.h>
#include <stdint.h>

// ---------------- problem constants ----------------
#define BB 32
#define MM 512
#define DD 512
#define HH 8
#define FF 8
#define CC 64           // DD / FF
#define TDD 4096        // FF * MM
#define MD (MM * DD)    // 262144

// ---------------- device scratch (no allocs allowed) ----------------
__device__ float g_x1 [(size_t)BB * MD];
__device__ float g_q  [(size_t)HH * BB * MD];
__device__ float g_k  [(size_t)HH * BB * MD];
__device__ float g_v  [(size_t)HH * BB * MD];
__device__ float g_s  [(size_t)HH * BB * MM * MM];
__device__ float g_cat[(size_t)BB * MM * HH * DD];
__device__ float g_x2 [(size_t)BB * MD];
__device__ float g_x3 [(size_t)BB * MD];
__device__ float g_t  [(size_t)BB * CC * TDD];
__device__ float g_tq [(size_t)BB * CC * TDD];
__device__ float g_tk [(size_t)BB * CC * TDD];
__device__ float g_tv [(size_t)BB * CC * TDD];
__device__ float g_s2 [(size_t)BB * CC * CC];
__device__ float g_t2 [(size_t)BB * CC * TDD];
__device__ float g_ff [BB];

// ---------------- RMSNorm (per-batch global norm) ----------------
__global__ void rms_reduce_k(const float* __restrict__ x, float* __restrict__ ff) {
    int b = blockIdx.x;
    const float* xb = x + (size_t)b * MD;
    float s = 0.f;
    for (int i = threadIdx.x; i < MD; i += blockDim.x) {
        float v = xb[i];
        s += v * v;
    }
    __shared__ float sm[32];
    for (int o = 16; o; o >>= 1) s += __shfl_xor_sync(0xffffffffu, s, o);
    if ((threadIdx.x & 31) == 0) sm[threadIdx.x >> 5] = s;
    __syncthreads();
    if (threadIdx.x < 32) {
        s = (threadIdx.x < (blockDim.x >> 5)) ? sm[threadIdx.x] : 0.f;
        for (int o = 16; o; o >>= 1) s += __shfl_xor_sync(0xffffffffu, s, o);
        if (threadIdx.x == 0) ff[b] = sqrtf((float)MD) * rsqrtf(s);
    }
}

__global__ void rms_apply_k(const float* __restrict__ x, const float* __restrict__ scale,
                            const float* __restrict__ ff, float* __restrict__ y) {
    long i = (long)blockIdx.x * blockDim.x + threadIdx.x;
    if (i >= (long)BB * MD) return;
    int b  = (int)(i / MD);
    int md = (int)(i % MD);
    y[i] = x[i] * scale[md] * ff[b];
}

// ---------------- RoPE (in place) ----------------
__global__ void rope_k(float* __restrict__ q, long total_pairs, int halfd, int angmod, float thc) {
    long idx = (long)blockIdx.x * blockDim.x + threadIdx.x;
    if (idx >= total_pairs) return;
    int  pair = (int)(idx % halfd);
    long row  = idx / halfd;
    int  a    = (int)(row % angmod);
    float theta = exp2f(thc * ((float)pair - 1.0f));
    float sn, cs;
    sincosf((float)a * theta, &sn, &cs);
    float* p = q + row * (long)(2 * halfd) + 2 * pair;
    float e = p[0], o = p[1];
    p[0] = fmaf(e, cs, o * sn);
    p[1] = fmaf(-e, sn, o * cs);
}

// ---------------- row softmax (warp per row) ----------------
__global__ void softmax_k(float* __restrict__ s, int L, long nrows) {
    long warp = (long)blockIdx.x * (blockDim.x >> 5) + (threadIdx.x >> 5);
    if (warp >= nrows) return;
    int lane = threadIdx.x & 31;
    float* row = s + warp * (long)L;
    float mx = -INFINITY;
    for (int i = lane; i < L; i += 32) mx = fmaxf(mx, row[i]);
    for (int o = 16; o; o >>= 1) mx = fmaxf(mx, __shfl_xor_sync(0xffffffffu, mx, o));
    float sum = 0.f;
    for (int i = lane; i < L; i += 32) {
        float e = __expf(row[i] - mx);
        row[i] = e;
        sum += e;
    }
    for (int o = 16; o; o >>= 1) sum += __shfl_xor_sync(0xffffffffu, sum, o);
    float inv = 1.f / sum;
    for (int i = lane; i < L; i += 32) row[i] *= inv;
}

// ==================== tf32 tensor-core GEMM ====================
// 128x128x32 block tile, 256 threads (8 warps as 2m x 4n), warp tile 64x32.
// mma.sync.m16n8k8 tf32, fp32 accumulate. rna rounding at smem store.
// A row-major [m][k]; B: TRANSB ? [n][k] : [k][n]. C row-major.
// Requires M,N % 128 == 0, K % 32 == 0.

__device__ __forceinline__ uint32_t cvta_smem_u32(const void* p) {
    uint32_t r;
    asm("{ .reg .u64 t; cvta.to.shared.u64 t, %1; cvt.u32.u64 %0, t; }" : "=r"(r) : "l"(p));
    return r;
}
__device__ __forceinline__ uint32_t f2tf(float f) {
    uint32_t r;
    asm("cvt.rna.tf32.f32 %0, %1;" : "=r"(r) : "f"(f));
    return r;
}
__device__ __forceinline__ void ldsm4(uint32_t r[4], uint32_t addr) {
    asm volatile("ldmatrix.sync.aligned.m8n8.x4.shared.b16 {%0,%1,%2,%3}, [%4];"
                 : "=r"(r[0]), "=r"(r[1]), "=r"(r[2]), "=r"(r[3]) : "r"(addr));
}
__device__ __forceinline__ void mma_tf32(float c[4], const uint32_t a[4], uint32_t b0, uint32_t b1) {
    asm volatile("mma.sync.aligned.m16n8k8.row.col.f32.tf32.tf32.f32 "
                 "{%0,%1,%2,%3}, {%4,%5,%6,%7}, {%8,%9}, {%0,%1,%2,%3};"
                 : "+f"(c[0]), "+f"(c[1]), "+f"(c[2]), "+f"(c[3])
                 : "r"(a[0]), "r"(a[1]), "r"(a[2]), "r"(a[3]), "r"(b0), "r"(b1));
}

#define TG_STAGE_U32 8192   // (128*32 A + 128*32 B) uint32 per stage
#define TG_SMEM_BYTES (2 * TG_STAGE_U32 * 4)

template<bool TRANSB, bool RES, bool BIAS>
__global__ void __launch_bounds__(256) tgemm_k(
    const float* __restrict__ A, int lda, long sAo, long sAi,
    const float* __restrict__ Bm, int ldb, long sBo, long sBi,
    float*       __restrict__ Cm, int ldc, long sCo, long sCi,
    const float* __restrict__ R, int ldr, long sRi,
    const float* __restrict__ bias,
    int K, int inner, float alpha)
{
    extern __shared__ uint32_t smem[];

    int z  = blockIdx.z;
    int zo = z / inner;
    int zi = z - zo * inner;
    A  += zo * sAo + zi * sAi;
    Bm += zo * sBo + zi * sBi;
    Cm += zo * sCo + zi * sCi;
    if (RES) R += (long)zi * sRi;

    const int tid  = threadIdx.x;
    const int lane = tid & 31;
    const int wid  = tid >> 5;
    const int warpM = wid & 1;        // 0..1 (64 rows)
    const int warpN = wid >> 1;       // 0..3 (32 cols)
    const int m0 = blockIdx.y << 7;
    const int n0 = blockIdx.x << 7;

    const uint32_t sbase = cvta_smem_u32(smem);

    // loader indices
    const int cA = tid & 7;           // chunk 0..7 (16B = 4 floats)
    const int rA = tid >> 3;          // row 0..31 (+32g)
    const int tB = tid >> 3;          // NN: n-chunk 0..31
    // fragment lane geometry
    const int lr = (lane & 7) + ((lane >> 3) & 1) * 8;  // row-in-16
    const int lc = lane >> 4;                            // chunk offset 0/1

    float4 pa[4], pb[4];

    float acc[4][4][4];
    #pragma unroll
    for (int i = 0; i < 4; i++)
        #pragma unroll
        for (int j = 0; j < 4; j++)
            #pragma unroll
            for (int r = 0; r < 4; r++) acc[i][j][r] = 0.f;

    const int niter = K >> 5;

    // --- prologue loads ---
    #pragma unroll
    for (int g = 0; g < 4; g++) {
        int r = rA + 32 * g;
        pa[g] = *reinterpret_cast<const float4*>(&A[(long)(m0 + r) * lda + cA * 4]);
        if (TRANSB)
            pb[g] = *reinterpret_cast<const float4*>(&Bm[(long)(n0 + r) * ldb + cA * 4]);
        else {
            int kk = (tid & 7) + 8 * g;
            pb[g] = *reinterpret_cast<const float4*>(&Bm[(long)kk * ldb + n0 + tB * 4]);
        }
    }
    // store stage 0
    {
        #pragma unroll
        for (int g = 0; g < 4; g++) {
            int r = rA + 32 * g;
            int ch = cA ^ (r & 7);
            uint32_t* d = &smem[r * 32 + ch * 4];
            d[0] = f2tf(pa[g].x); d[1] = f2tf(pa[g].y); d[2] = f2tf(pa[g].z); d[3] = f2tf(pa[g].w);
            if (TRANSB) {
                uint32_t* d2 = &smem[4096 + r * 32 + ch * 4];
                d2[0] = f2tf(pb[g].x); d2[1] = f2tf(pb[g].y); d2[2] = f2tf(pb[g].z); d2[3] = f2tf(pb[g].w);
            } else {
                int kk = (tid & 7) + 8 * g;
                float vv[4] = {pb[g].x, pb[g].y, pb[g].z, pb[g].w};
                #pragma unroll
                for (int j = 0; j < 4; j++) {
                    int n = tB * 4 + j;
                    smem[4096 + n * 32 + (((kk >> 2) ^ (n & 7)) << 2) + (kk & 3)] = f2tf(vv[j]);
                }
            }
        }
    }
    __syncthreads();

    for (int it = 0; it < niter; it++) {
        int st = it & 1;
        // prefetch next tile
        if (it + 1 < niter) {
            int k0 = (it + 1) << 5;
            #pragma unroll
            for (int g = 0; g < 4; g++) {
                int r = rA + 32 * g;
                pa[g] = *reinterpret_cast<const float4*>(&A[(long)(m0 + r) * lda + k0 + cA * 4]);
                if (TRANSB)
                    pb[g] = *reinterpret_cast<const float4*>(&Bm[(long)(n0 + r) * ldb + k0 + cA * 4]);
                else {
                    int kk = (tid & 7) + 8 * g;
                    pb[g] = *reinterpret_cast<const float4*>(&Bm[(long)(k0 + kk) * ldb + n0 + tB * 4]);
                }
            }
        }

        // compute current stage
        {
            const uint32_t baseA = sbase + (uint32_t)st * TG_STAGE_U32 * 4;
            const uint32_t baseB = baseA + 4096 * 4;
            #pragma unroll
            for (int s = 0; s < 4; s++) {
                uint32_t af[4][4], bq[2][4];
                #pragma unroll
                for (int i = 0; i < 4; i++) {
                    int row = warpM * 64 + i * 16 + lr;
                    int ch  = (2 * s + lc) ^ (row & 7);
                    ldsm4(af[i], baseA + (uint32_t)(row * 32 + ch * 4) * 4);
                }
                #pragma unroll
                for (int p = 0; p < 2; p++) {
                    int row = warpN * 32 + p * 16 + lr;
                    int ch  = (2 * s + lc) ^ (row & 7);
                    ldsm4(bq[p], baseB + (uint32_t)(row * 32 + ch * 4) * 4);
                }
                #pragma unroll
                for (int i = 0; i < 4; i++)
                    #pragma unroll
                    for (int j = 0; j < 4; j++)
                        mma_tf32(acc[i][j], af[i], bq[j >> 1][j & 1], bq[j >> 1][2 + (j & 1)]);
            }
        }

        // store next stage
        if (it + 1 < niter) {
            uint32_t* sn = &smem[(st ^ 1) * TG_STAGE_U32];
            #pragma unroll
            for (int g = 0; g < 4; g++) {
                int r = rA + 32 * g;
                int ch = cA ^ (r & 7);
                uint32_t* d = &sn[r * 32 + ch * 4];
                d[0] = f2tf(pa[g].x); d[1] = f2tf(pa[g].y); d[2] = f2tf(pa[g].z); d[3] = f2tf(pa[g].w);
                if (TRANSB) {
                    uint32_t* d2 = &sn[4096 + r * 32 + ch * 4];
                    d2[0] = f2tf(pb[g].x); d2[1] = f2tf(pb[g].y); d2[2] = f2tf(pb[g].z); d2[3] = f2tf(pb[g].w);
                } else {
                    int kk = (tid & 7) + 8 * g;
                    float vv[4] = {pb[g].x, pb[g].y, pb[g].z, pb[g].w};
                    #pragma unroll
                    for (int j = 0; j < 4; j++) {
                        int n = tB * 4 + j;
                        sn[4096 + n * 32 + (((kk >> 2) ^ (n & 7)) << 2) + (kk & 3)] = f2tf(vv[j]);
                    }
                }
            }
        }
        __syncthreads();
    }

    // --- epilogue ---
    const int g8 = lane >> 2;
    const int t4 = lane & 3;
    #pragma unroll
    for (int i = 0; i < 4; i++) {
        int mrow = m0 + warpM * 64 + i * 16 + g8;
        #pragma unroll
        for (int j = 0; j < 4; j++) {
            int col = n0 + warpN * 32 + j * 8 + 2 * t4;
            float v0 = acc[i][j][0] * alpha;
            float v1 = acc[i][j][1] * alpha;
            float v2 = acc[i][j][2] * alpha;
            float v3 = acc[i][j][3] * alpha;
            if (RES) {
                v0 += R[(long)mrow * ldr + col];
                v1 += R[(long)mrow * ldr + col + 1];
                v2 += R[(long)(mrow + 8) * ldr + col];
                v3 += R[(long)(mrow + 8) * ldr + col + 1];
            }
            if (BIAS) {
                v0 += bias[col]; v1 += bias[col + 1];
                v2 += bias[col]; v3 += bias[col + 1];
            }
            *reinterpret_cast<float2*>(&Cm[(long)mrow * ldc + col])      = make_float2(v0, v1);
            *reinterpret_cast<float2*>(&Cm[(long)(mrow + 8) * ldc + col]) = make_float2(v2, v3);
        }
    }
}

// ================= small SGEMM: 64x64 tile fp32 (stage-2 attn) =====
template<bool TRANSB, bool RES, bool BIAS>
__global__ void __launch_bounds__(256) sgemm_k(
    const float* __restrict__ A, int lda, long sAo, long sAi,
    const float* __restrict__ Bm, int ldb, long sBo, long sBi,
    float*       __restrict__ Cm, int ldc, long sCo, long sCi,
    const float* __restrict__ R, int ldr, long sRi,
    const float* __restrict__ bias,
    int K, int inner, float alpha)
{
    int z  = blockIdx.z;
    int zo = z / inner;
    int zi = z - zo * inner;
    A  += zo * sAo + zi * sAi;
    Bm += zo * sBo + zi * sBi;
    Cm += zo * sCo + zi * sCi;
    if (RES) R += (long)zi * sRi;

    __shared__ __align__(16) float As[16][68];
    __shared__ __align__(16) float Bs[16][68];

    const int tid = threadIdx.x;
    const int m0 = blockIdx.y << 6;
    const int n0 = blockIdx.x << 6;
    const int tx = tid & 15, ty = tid >> 4;

    const int ar = tid >> 2;
    const int ac = (tid & 3) << 2;
    const int br = tid >> 4;
    const int bc = (tid & 15) << 2;

    float acc[4][4] = {};

    for (int k0 = 0; k0 < K; k0 += 16) {
        float4 av = *reinterpret_cast<const float4*>(&A[(long)(m0 + ar) * lda + k0 + ac]);
        As[ac + 0][ar] = av.x; As[ac + 1][ar] = av.y;
        As[ac + 2][ar] = av.z; As[ac + 3][ar] = av.w;
        if (!TRANSB) {
            float4 bv = *reinterpret_cast<const float4*>(&Bm[(long)(k0 + br) * ldb + n0 + bc]);
            *reinterpret_cast<float4*>(&Bs[br][bc]) = bv;
        } else {
            float4 bv = *reinterpret_cast<const float4*>(&Bm[(long)(n0 + ar) * ldb + k0 + ac]);
            Bs[ac + 0][ar] = bv.x; Bs[ac + 1][ar] = bv.y;
            Bs[ac + 2][ar] = bv.z; Bs[ac + 3][ar] = bv.w;
        }
        __syncthreads();
        #pragma unroll
        for (int k = 0; k < 16; k++) {
            float4 a4 = *reinterpret_cast<const float4*>(&As[k][ty << 2]);
            float4 b4 = *reinterpret_cast<const float4*>(&Bs[k][tx << 2]);
            float a[4] = {a4.x, a4.y, a4.z, a4.w};
            float b[4] = {b4.x, b4.y, b4.z, b4.w};
            #pragma unroll
            for (int i = 0; i < 4; i++)
                #pragma unroll
                for (int j = 0; j < 4; j++)
                    acc[i][j] = fmaf(a[i], b[j], acc[i][j]);
        }
        __syncthreads();
    }

    #pragma unroll
    for (int i = 0; i < 4; i++) {
        int m = m0 + (ty << 2) + i;
        #pragma unroll
        for (int j = 0; j < 4; j++) {
            int n = n0 + (tx << 2) + j;
            float v = acc[i][j] * alpha;
            if (RES)  v += R[(long)m * ldr + n];
            if (BIAS) v += bias[n];
            Cm[(long)m * ldc + n] = v;
        }
    }
}

// ---------------- layout shuffles ----------------
__global__ void build_t_k(const float* __restrict__ x3, float* __restrict__ t) {
    long i = (long)blockIdx.x * blockDim.x + threadIdx.x;
    if (i >= (long)BB * CC * TDD) return;
    int  j  = (int)(i % TDD);
    long bc = i / TDD;
    int  c  = (int)(bc % CC);
    int  b  = (int)(bc / CC);
    int  p  = j >> 9;
    int  m  = j & 511;
    t[i] = x3[(long)b * MD + (long)m * DD + c * FF + p];
}

__global__ void build_out_k(const float* __restrict__ t2, float* __restrict__ out) {
    long i = (long)blockIdx.x * blockDim.x + threadIdx.x;
    if (i >= (long)BB * MD) return;
    int  d  = (int)(i % DD);
    long bm = i / DD;
    int  m  = (int)(bm % MM);
    int  b  = (int)(bm / MM);
    int  c  = d >> 3;
    int  p  = d & 7;
    out[i] = t2[(long)b * (CC * TDD) + (long)c * TDD + p * MM + m];
}

// ---------------- launch ----------------
extern "C" void kernel_launch(void* const* d_in, const int* in_sizes, int n_in,
                              void* d_out, int out_size) {
    const float* x     = (const float*)d_in[0];
    const float* scale = (const float*)d_in[1];
    const float* wq    = (const float*)d_in[2];
    const float* wk    = (const float*)d_in[3];
    const float* wv    = (const float*)d_in[4];
    const float* lin_w = (const float*)d_in[5];
    const float* lin_b = (const float*)d_in[6];
    const float* twq   = (const float*)d_in[7];
    const float* twk   = (const float*)d_in[8];
    const float* twv   = (const float*)d_in[9];
    float* out = (float*)d_out;

    float *x1, *q, *k, *v, *s, *cat, *x2, *x3, *t, *tq, *tk, *tv, *s2, *t2, *ff;
    cudaGetSymbolAddress((void**)&x1,  g_x1);
    cudaGetSymbolAddress((void**)&q,   g_q);
    cudaGetSymbolAddress((void**)&k,   g_k);
    cudaGetSymbolAddress((void**)&v,   g_v);
    cudaGetSymbolAddress((void**)&s,   g_s);
    cudaGetSymbolAddress((void**)&cat, g_cat);
    cudaGetSymbolAddress((void**)&x2,  g_x2);
    cudaGetSymbolAddress((void**)&x3,  g_x3);
    cudaGetSymbolAddress((void**)&t,   g_t);
    cudaGetSymbolAddress((void**)&tq,  g_tq);
    cudaGetSymbolAddress((void**)&tk,  g_tk);
    cudaGetSymbolAddress((void**)&tv,  g_tv);
    cudaGetSymbolAddress((void**)&s2,  g_s2);
    cudaGetSymbolAddress((void**)&t2,  g_t2);
    cudaGetSymbolAddress((void**)&ff,  g_ff);

    // raise dynamic smem limits for tgemm instantiations (idempotent)
    cudaFuncSetAttribute(tgemm_k<false,false,false>, cudaFuncAttributeMaxDynamicSharedMemorySize, TG_SMEM_BYTES);
    cudaFuncSetAttribute(tgemm_k<true, false,false>, cudaFuncAttributeMaxDynamicSharedMemorySize, TG_SMEM_BYTES);
    cudaFuncSetAttribute(tgemm_k<false,true, true >, cudaFuncAttributeMaxDynamicSharedMemorySize, TG_SMEM_BYTES);

    const float th1 = -2.0f * log2f(10000.0f) / (float)DD;
    const float th2 = -2.0f * log2f(10000.0f) / (float)TDD;
    const float al1 = 1.0f / sqrtf((float)DD);
    const float al2 = 1.0f / sqrtf((float)TDD);

    // 1) x1 = rmsnorm(x)
    rms_reduce_k<<<BB, 1024>>>(x, ff);
    rms_apply_k<<<(BB * MD) / 256, 256>>>(x, scale, ff, x1);

    // 2) q/k/v[h,b] = x1[b] @ w[h]   (NN, z = h*BB + b)
    {
        dim3 g(DD / 128, MM / 128, HH * BB);
        tgemm_k<false,false,false><<<g, 256, TG_SMEM_BYTES>>>(x1, DD, 0, MD, wq, DD, (long)MD, 0,
                                                              q, DD, (long)BB * MD, MD,
                                                              nullptr, 0, 0, nullptr, DD, BB, 1.f);
        tgemm_k<false,false,false><<<g, 256, TG_SMEM_BYTES>>>(x1, DD, 0, MD, wk, DD, (long)MD, 0,
                                                              k, DD, (long)BB * MD, MD,
                                                              nullptr, 0, 0, nullptr, DD, BB, 1.f);
        tgemm_k<false,false,false><<<g, 256, TG_SMEM_BYTES>>>(x1, DD, 0, MD, wv, DD, (long)MD, 0,
                                                              v, DD, (long)BB * MD, MD,
                                                              nullptr, 0, 0, nullptr, DD, BB, 1.f);
    }

    // 3) RoPE on q,k
    {
        long tp = (long)HH * BB * MM * (DD / 2);
        int blocks = (int)((tp + 255) / 256);
        rope_k<<<blocks, 256>>>(q, tp, DD / 2, MM, th1);
        rope_k<<<blocks, 256>>>(k, tp, DD / 2, MM, th1);
    }

    // 4) S = (q/sqrt(D)) @ k^T (TRANSB); softmax; O = P @ v (NN, into cat layout)
    {
        dim3 g(MM / 128, MM / 128, HH * BB);
        tgemm_k<true,false,false><<<g, 256, TG_SMEM_BYTES>>>(q, DD, (long)BB * MD, MD,
                                                             k, DD, (long)BB * MD, MD,
                                                             s, MM, (long)BB * MM * MM, (long)MM * MM,
                                                             nullptr, 0, 0, nullptr, DD, BB, al1);
        long nrows = (long)HH * BB * MM;
        softmax_k<<<(int)(nrows / 8), 256>>>(s, MM, nrows);
        dim3 g2(DD / 128, MM / 128, HH * BB);
        tgemm_k<false,false,false><<<g2, 256, TG_SMEM_BYTES>>>(s, MM, (long)BB * MM * MM, (long)MM * MM,
                                                               v, DD, (long)BB * MD, MD,
                                                               cat, HH * DD, (long)DD, (long)MM * HH * DD,
                                                               nullptr, 0, 0, nullptr, MM, BB, 1.f);
    }

    // 5) x2 = x1 + cat @ lin_w + lin_b   (M=16384, N=512, K=4096)
    {
        dim3 g(DD / 128, (BB * MM) / 128, 1);
        tgemm_k<false,true,true><<<g, 256, TG_SMEM_BYTES>>>(cat, HH * DD, 0, 0, lin_w, DD, 0, 0,
                                                            x2, DD, 0, 0,
                                                            x1, DD, 0, lin_b, HH * DD, 1, 1.f);
    }

    // 6) x3 = rmsnorm(x2)
    rms_reduce_k<<<BB, 1024>>>(x2, ff);
    rms_apply_k<<<(BB * MD) / 256, 256>>>(x2, scale, ff, x3);

    // 7) t  (channel transpose)
    build_t_k<<<(int)(((long)BB * CC * TDD) / 256), 256>>>(x3, t);

    // 8) tq/tk/tv = t @ tw   (M=2048, N=4096, K=4096)
    {
        dim3 g(TDD / 128, (BB * CC) / 128, 1);
        tgemm_k<false,false,false><<<g, 256, TG_SMEM_BYTES>>>(t, TDD, 0, 0, twq, TDD, 0, 0, tq, TDD, 0, 0,
                                                              nullptr, 0, 0, nullptr, TDD, 1, 1.f);
        tgemm_k<false,false,false><<<g, 256, TG_SMEM_BYTES>>>(t, TDD, 0, 0, twk, TDD, 0, 0, tk, TDD, 0, 0,
                                                              nullptr, 0, 0, nullptr, TDD, 1, 1.f);
        tgemm_k<false,false,false><<<g, 256, TG_SMEM_BYTES>>>(t, TDD, 0, 0, twv, TDD, 0, 0, tv, TDD, 0, 0,
                                                              nullptr, 0, 0, nullptr, TDD, 1, 1.f);
    }

    // 9) RoPE on tq,tk
    {
        long tp = (long)BB * CC * (TDD / 2);
        int blocks = (int)((tp + 255) / 256);
        rope_k<<<blocks, 256>>>(tq, tp, TDD / 2, CC, th2);
        rope_k<<<blocks, 256>>>(tk, tp, TDD / 2, CC, th2);
    }

    // 10) S2 = (tq/64) @ tk^T per batch; softmax; t2 = t + P2 @ tv
    {
        dim3 g(1, 1, BB);
        sgemm_k<true,false,false><<<g, 256>>>(tq, TDD, 0, (long)CC * TDD,
                                              tk, TDD, 0, (long)CC * TDD,
                                              s2, CC, 0, (long)CC * CC,
                                              nullptr, 0, 0, nullptr, TDD, BB, al2);
        softmax_k<<<(BB * CC) / 8, 256>>>(s2, CC, (long)BB * CC);
        dim3 g2(TDD / 64, 1, BB);
        sgemm_k<false,true,false><<<g2, 256>>>(s2, CC, 0, (long)CC * CC,
                                               tv, TDD, 0, (long)CC * TDD,
                                               t2, TDD, 0, (long)CC * TDD,
                                               t, TDD, (long)CC * TDD, nullptr,
                                               CC, BB, 1.f);
    }

    // 11) inverse transpose into d_out
    build_out_k<<<(int)(((long)BB * MD) / 256), 256>>>(t2, out);
}

// round 5
// speedup vs baseline: 3.2450x; 1.9481x over previous
#include <cuda_runtime.h>
#include <math.h>
#include <stdint.h>

// ---------------- problem constants ----------------
#define BB 32
#define MM 512
#define DD 512
#define HH 8
#define FF 8
#define CC 64           // DD / FF
#define TDD 4096        // FF * MM
#define MD (MM * DD)    // 262144

// ---------------- device scratch (no allocs allowed) ----------------
__device__ float g_x1 [(size_t)BB * MD];
__device__ float g_q  [(size_t)HH * BB * MD];
__device__ float g_k  [(size_t)HH * BB * MD];
__device__ float g_v  [(size_t)HH * BB * MD];
__device__ float g_s  [(size_t)HH * BB * MM * MM];
__device__ float g_cat[(size_t)BB * MM * HH * DD];
__device__ float g_x2 [(size_t)BB * MD];
__device__ float g_x3 [(size_t)BB * MD];
__device__ float g_t  [(size_t)BB * CC * TDD];
__device__ float g_tq [(size_t)BB * CC * TDD];
__device__ float g_tk [(size_t)BB * CC * TDD];
__device__ float g_tv [(size_t)BB * CC * TDD];
__device__ float g_s2 [(size_t)BB * CC * CC];
__device__ float g_s2p[(size_t)8 * BB * CC * CC];
__device__ float g_t2 [(size_t)BB * CC * TDD];
__device__ float g_ff [BB];
// tf32-rounded weight copies
__device__ float g_rwq[(size_t)HH * DD * DD];
__device__ float g_rwk[(size_t)HH * DD * DD];
__device__ float g_rwv[(size_t)HH * DD * DD];
__device__ float g_rlw[(size_t)HH * DD * DD];      // 4096*512
__device__ float g_rtwq[(size_t)TDD * TDD];
__device__ float g_rtwk[(size_t)TDD * TDD];
__device__ float g_rtwv[(size_t)TDD * TDD];

// ---------------- tf32 helpers ----------------
__device__ __forceinline__ uint32_t f2tf(float f) {
    uint32_t r;
    asm("cvt.rna.tf32.f32 %0, %1;" : "=r"(r) : "f"(f));
    return r;
}
__device__ __forceinline__ float rndtf(float f) { return __uint_as_float(f2tf(f)); }

__device__ __forceinline__ uint32_t cvta_smem_u32(const void* p) {
    uint32_t r;
    asm("{ .reg .u64 t; cvta.to.shared.u64 t, %1; cvt.u32.u64 %0, t; }" : "=r"(r) : "l"(p));
    return r;
}
__device__ __forceinline__ void ldsm4(uint32_t r[4], uint32_t addr) {
    asm volatile("ldmatrix.sync.aligned.m8n8.x4.shared.b16 {%0,%1,%2,%3}, [%4];"
                 : "=r"(r[0]), "=r"(r[1]), "=r"(r[2]), "=r"(r[3]) : "r"(addr));
}
__device__ __forceinline__ uint32_t lds32(uint32_t addr) {
    uint32_t v;
    asm volatile("ld.shared.b32 %0, [%1];" : "=r"(v) : "r"(addr));
    return v;
}
__device__ __forceinline__ void mma_tf32(float c[4], const uint32_t a[4], uint32_t b0, uint32_t b1) {
    asm volatile("mma.sync.aligned.m16n8k8.row.col.f32.tf32.tf32.f32 "
                 "{%0,%1,%2,%3}, {%4,%5,%6,%7}, {%8,%9}, {%0,%1,%2,%3};"
                 : "+f"(c[0]), "+f"(c[1]), "+f"(c[2]), "+f"(c[3])
                 : "r"(a[0]), "r"(a[1]), "r"(a[2]), "r"(a[3]), "r"(b0), "r"(b1));
}
#define CP16(dst, src) asm volatile("cp.async.cg.shared.global [%0], [%1], 16;" :: "r"(dst), "l"(src))
#define CP_COMMIT()    asm volatile("cp.async.commit_group;")
#define CP_WAIT1()     asm volatile("cp.async.wait_group 1;")

// ---------------- weight tf32 rounding (per launch, into scratch) ----------------
__global__ void roundw_k(const float* __restrict__ s, float* __restrict__ d, long n) {
    long stride = (long)gridDim.x * blockDim.x;
    for (long i = (long)blockIdx.x * blockDim.x + threadIdx.x; i < n; i += stride)
        d[i] = rndtf(s[i]);
}

// ---------------- RMSNorm ----------------
__global__ void rms_reduce_k(const float* __restrict__ x, float* __restrict__ ff) {
    int b = blockIdx.x;
    const float* xb = x + (size_t)b * MD;
    float s = 0.f;
    for (int i = threadIdx.x; i < MD; i += blockDim.x) {
        float v = xb[i];
        s += v * v;
    }
    __shared__ float sm[32];
    for (int o = 16; o; o >>= 1) s += __shfl_xor_sync(0xffffffffu, s, o);
    if ((threadIdx.x & 31) == 0) sm[threadIdx.x >> 5] = s;
    __syncthreads();
    if (threadIdx.x < 32) {
        s = (threadIdx.x < (blockDim.x >> 5)) ? sm[threadIdx.x] : 0.f;
        for (int o = 16; o; o >>= 1) s += __shfl_xor_sync(0xffffffffu, s, o);
        if (threadIdx.x == 0) ff[b] = sqrtf((float)MD) * rsqrtf(s);
    }
}

// output rounded to tf32 (feeds tensor GEMMs)
__global__ void rms_apply_k(const float* __restrict__ x, const float* __restrict__ scale,
                            const float* __restrict__ ff, float* __restrict__ y) {
    long i = (long)blockIdx.x * blockDim.x + threadIdx.x;
    if (i >= (long)BB * MD) return;
    int b  = (int)(i / MD);
    int md = (int)(i % MD);
    y[i] = rndtf(x[i] * scale[md] * ff[b]);
}

// ---------------- RoPE (in place), optional tf32 rounding of output ----------------
__global__ void rope_k(float* __restrict__ q, long total_pairs, int halfd, int angmod,
                       float thc, int doRound) {
    long idx = (long)blockIdx.x * blockDim.x + threadIdx.x;
    if (idx >= total_pairs) return;
    int  pair = (int)(idx % halfd);
    long row  = idx / halfd;
    int  a    = (int)(row % angmod);
    float theta = exp2f(thc * ((float)pair - 1.0f));
    float sn, cs;
    sincosf((float)a * theta, &sn, &cs);
    float* p = q + row * (long)(2 * halfd) + 2 * pair;
    float e = p[0], o = p[1];
    float r0 = fmaf(e, cs, o * sn);
    float r1 = fmaf(-e, sn, o * cs);
    if (doRound) { r0 = rndtf(r0); r1 = rndtf(r1); }
    p[0] = r0;
    p[1] = r1;
}

// ---------------- row softmax (warp per row), optional tf32 rounding ----------------
__global__ void softmax_k(float* __restrict__ s, int L, long nrows, int doRound) {
    long warp = (long)blockIdx.x * (blockDim.x >> 5) + (threadIdx.x >> 5);
    if (warp >= nrows) return;
    int lane = threadIdx.x & 31;
    float* row = s + warp * (long)L;
    float mx = -INFINITY;
    for (int i = lane; i < L; i += 32) mx = fmaxf(mx, row[i]);
    for (int o = 16; o; o >>= 1) mx = fmaxf(mx, __shfl_xor_sync(0xffffffffu, mx, o));
    float sum = 0.f;
    for (int i = lane; i < L; i += 32) {
        float e = __expf(row[i] - mx);
        row[i] = e;
        sum += e;
    }
    for (int o = 16; o; o >>= 1) sum += __shfl_xor_sync(0xffffffffu, sum, o);
    float inv = 1.f / sum;
    for (int i = lane; i < L; i += 32) {
        float vv = row[i] * inv;
        row[i] = doRound ? rndtf(vv) : vv;
    }
}

// ==================== tf32 tensor-core GEMM, cp.async 3-stage ====================
// Inputs must already be tf32-rounded fp32 bit patterns in gmem.
// 128x128x32 block tile, 256 thr (8 warps 2m x 4n), warp tile 64x32.
// A row-major [m][k]; B: TRANSB ? [n][k] (n-major smem + ldmatrix)
//                        : [k][n] (k-major smem pitch 136 + direct LDS fragments).
// M,N % 128 == 0, K % 32 == 0, K >= 64.

#define NSTG   3
#define A_STG  4096                      // u32 per stage (128 rows x 32)
#define B_STG  4352                      // u32 per stage (32 rows x 136 for NN; TRANSB uses 4096)
#define STG_U32 (A_STG + B_STG)          // 8448
#define TG_SMEM (NSTG * STG_U32 * 4)     // 101376 bytes

template<bool TRANSB, bool RES, bool BIAS, bool ROUND>
__global__ void __launch_bounds__(256, 2) tg_k(
    const float* __restrict__ A, int lda, long sAo, long sAi,
    const float* __restrict__ Bm, int ldb, long sBo, long sBi,
    float*       __restrict__ Cm, int ldc, long sCo, long sCi,
    const float* __restrict__ R, int ldr, long sRi,
    const float* __restrict__ bias,
    int K, int inner, float alpha)
{
    extern __shared__ uint32_t smem[];

    int z  = blockIdx.z;
    int zo = z / inner;
    int zi = z - zo * inner;
    A  += zo * sAo + zi * sAi;
    Bm += zo * sBo + zi * sBi;
    Cm += zo * sCo + zi * sCi;
    if (RES) R += (long)zi * sRi;

    const int tid  = threadIdx.x;
    const int lane = tid & 31;
    const int wid  = tid >> 5;
    const int warpM = wid & 1;
    const int warpN = wid >> 1;
    const int m0 = blockIdx.y << 7;
    const int n0 = blockIdx.x << 7;

    const uint32_t sbase = cvta_smem_u32(smem);

    const int cA = tid & 7;     // 16B chunk 0..7
    const int rA = tid >> 3;    // row 0..31
    // fragment lane geometry (validated round 3)
    const int lr = (lane & 7) + ((lane >> 3) & 1) * 8;
    const int lc = lane >> 4;
    // NN B fragment per-thread base offset (u32 units within B stage)
    const int bfrag = (lane & 3) * 136 + warpN * 32 + (lane >> 2);

    float acc[4][4][4];
    #pragma unroll
    for (int i = 0; i < 4; i++)
        #pragma unroll
        for (int j = 0; j < 4; j++)
            #pragma unroll
            for (int r = 0; r < 4; r++) acc[i][j][r] = 0.f;

    const int niter = K >> 5;

    // ---- async load of one 128x32 A-tile + B-tile into stage st ----
    #define TG_ISSUE(st, k0)                                                          \
    {                                                                                 \
        uint32_t sA = sbase + (uint32_t)(st) * STG_U32 * 4;                           \
        uint32_t sB = sA + A_STG * 4;                                                 \
        _Pragma("unroll")                                                             \
        for (int g = 0; g < 4; g++) {                                                 \
            int r = rA + 32 * g;                                                      \
            int ch = cA ^ (r & 7);                                                    \
            CP16(sA + (uint32_t)(r * 32 + ch * 4) * 4,                                \
                 &A[(long)(m0 + r) * lda + (k0) + cA * 4]);                           \
            if (TRANSB) {                                                             \
                CP16(sB + (uint32_t)(r * 32 + ch * 4) * 4,                            \
                     &Bm[(long)(n0 + r) * ldb + (k0) + cA * 4]);                      \
            } else {                                                                  \
                int c = cA + 8 * g;                                                   \
                CP16(sB + (uint32_t)(rA * 136 + c * 4) * 4,                           \
                     &Bm[(long)((k0) + rA) * ldb + n0 + c * 4]);                      \
            }                                                                         \
        }                                                                             \
    }

    TG_ISSUE(0, 0);  CP_COMMIT();
    TG_ISSUE(1, 32); CP_COMMIT();

    for (int it = 0; it < niter; it++) {
        CP_WAIT1();
        __syncthreads();

        int nx = it + 2;
        if (nx < niter) { TG_ISSUE(nx % NSTG, nx << 5); }
        CP_COMMIT();   // empty group near the tail keeps wait_group<1> uniform

        int st = it % NSTG;
        const uint32_t baseA = sbase + (uint32_t)st * STG_U32 * 4;
        const uint32_t baseB = baseA + A_STG * 4;
        #pragma unroll
        for (int s = 0; s < 4; s++) {
            uint32_t af[4][4];
            #pragma unroll
            for (int i = 0; i < 4; i++) {
                int row = warpM * 64 + i * 16 + lr;
                int ch  = (2 * s + lc) ^ (row & 7);
                ldsm4(af[i], baseA + (uint32_t)(row * 32 + ch * 4) * 4);
            }
            if (TRANSB) {
                uint32_t bq[2][4];
                #pragma unroll
                for (int p = 0; p < 2; p++) {
                    int row = warpN * 32 + p * 16 + lr;
                    int ch  = (2 * s + lc) ^ (row & 7);
                    ldsm4(bq[p], baseB + (uint32_t)(row * 32 + ch * 4) * 4);
                }
                #pragma unroll
                for (int i = 0; i < 4; i++)
                    #pragma unroll
                    for (int j = 0; j < 4; j++)
                        mma_tf32(acc[i][j], af[i], bq[j >> 1][j & 1], bq[j >> 1][2 + (j & 1)]);
            } else {
                uint32_t b0[4], b1[4];
                #pragma unroll
                for (int j = 0; j < 4; j++) {
                    uint32_t ad = baseB + (uint32_t)(s * 8 * 136 + bfrag + j * 8) * 4;
                    b0[j] = lds32(ad);
                    b1[j] = lds32(ad + 544 * 4);   // +4 k-rows * pitch 136
                }
                #pragma unroll
                for (int i = 0; i < 4; i++)
                    #pragma unroll
                    for (int j = 0; j < 4; j++)
                        mma_tf32(acc[i][j], af[i], b0[j], b1[j]);
            }
        }
    }
    #undef TG_ISSUE

    // --- epilogue ---
    const int g8 = lane >> 2;
    const int t4 = lane & 3;
    #pragma unroll
    for (int i = 0; i < 4; i++) {
        int mrow = m0 + warpM * 64 + i * 16 + g8;
        #pragma unroll
        for (int j = 0; j < 4; j++) {
            int col = n0 + warpN * 32 + j * 8 + 2 * t4;
            float v0 = acc[i][j][0] * alpha;
            float v1 = acc[i][j][1] * alpha;
            float v2 = acc[i][j][2] * alpha;
            float v3 = acc[i][j][3] * alpha;
            if (RES) {
                v0 += R[(long)mrow * ldr + col];
                v1 += R[(long)mrow * ldr + col + 1];
                v2 += R[(long)(mrow + 8) * ldr + col];
                v3 += R[(long)(mrow + 8) * ldr + col + 1];
            }
            if (BIAS) {
                v0 += bias[col]; v1 += bias[col + 1];
                v2 += bias[col]; v3 += bias[col + 1];
            }
            if (ROUND) { v0 = rndtf(v0); v1 = rndtf(v1); v2 = rndtf(v2); v3 = rndtf(v3); }
            *reinterpret_cast<float2*>(&Cm[(long)mrow * ldc + col])       = make_float2(v0, v1);
            *reinterpret_cast<float2*>(&Cm[(long)(mrow + 8) * ldc + col]) = make_float2(v2, v3);
        }
    }
}

// ================= small fp32 SGEMM: 64x64 tile (stage-2 attn) =====
template<bool TRANSB, bool RES, bool BIAS>
__global__ void __launch_bounds__(256) sgemm_k(
    const float* __restrict__ A, int lda, long sAo, long sAi,
    const float* __restrict__ Bm, int ldb, long sBo, long sBi,
    float*       __restrict__ Cm, int ldc, long sCo, long sCi,
    const float* __restrict__ R, int ldr, long sRi,
    const float* __restrict__ bias,
    int K, int inner, float alpha)
{
    int z  = blockIdx.z;
    int zo = z / inner;
    int zi = z - zo * inner;
    A  += zo * sAo + zi * sAi;
    Bm += zo * sBo + zi * sBi;
    Cm += zo * sCo + zi * sCi;
    if (RES) R += (long)zi * sRi;

    __shared__ __align__(16) float As[16][68];
    __shared__ __align__(16) float Bs[16][68];

    const int tid = threadIdx.x;
    const int m0 = blockIdx.y << 6;
    const int n0 = blockIdx.x << 6;
    const int tx = tid & 15, ty = tid >> 4;

    const int ar = tid >> 2;
    const int ac = (tid & 3) << 2;
    const int br = tid >> 4;
    const int bc = (tid & 15) << 2;

    float acc[4][4] = {};

    for (int k0 = 0; k0 < K; k0 += 16) {
        float4 av = *reinterpret_cast<const float4*>(&A[(long)(m0 + ar) * lda + k0 + ac]);
        As[ac + 0][ar] = av.x; As[ac + 1][ar] = av.y;
        As[ac + 2][ar] = av.z; As[ac + 3][ar] = av.w;
        if (!TRANSB) {
            float4 bv = *reinterpret_cast<const float4*>(&Bm[(long)(k0 + br) * ldb + n0 + bc]);
            *reinterpret_cast<float4*>(&Bs[br][bc]) = bv;
        } else {
            float4 bv = *reinterpret_cast<const float4*>(&Bm[(long)(n0 + ar) * ldb + k0 + ac]);
            Bs[ac + 0][ar] = bv.x; Bs[ac + 1][ar] = bv.y;
            Bs[ac + 2][ar] = bv.z; Bs[ac + 3][ar] = bv.w;
        }
        __syncthreads();
        #pragma unroll
        for (int k = 0; k < 16; k++) {
            float4 a4 = *reinterpret_cast<const float4*>(&As[k][ty << 2]);
            float4 b4 = *reinterpret_cast<const float4*>(&Bs[k][tx << 2]);
            float a[4] = {a4.x, a4.y, a4.z, a4.w};
            float b[4] = {b4.x, b4.y, b4.z, b4.w};
            #pragma unroll
            for (int i = 0; i < 4; i++)
                #pragma unroll
                for (int j = 0; j < 4; j++)
                    acc[i][j] = fmaf(a[i], b[j], acc[i][j]);
        }
        __syncthreads();
    }

    #pragma unroll
    for (int i = 0; i < 4; i++) {
        int m = m0 + (ty << 2) + i;
        #pragma unroll
        for (int j = 0; j < 4; j++) {
            int n = n0 + (tx << 2) + j;
            float v = acc[i][j] * alpha;
            if (RES)  v += R[(long)m * ldr + n];
            if (BIAS) v += bias[n];
            Cm[(long)m * ldc + n] = v;
        }
    }
}

// ---------------- stage-2 split-K reduce ----------------
__global__ void s2red_k(const float* __restrict__ p, float* __restrict__ o) {
    long i = (long)blockIdx.x * blockDim.x + threadIdx.x;
    if (i >= (long)BB * CC * CC) return;
    float s = 0.f;
    #pragma unroll
    for (int ks = 0; ks < 8; ks++) s += p[(long)ks * BB * CC * CC + i];
    o[i] = s;
}

// ---------------- layout shuffles ----------------
__global__ void build_t_k(const float* __restrict__ x3, float* __restrict__ t) {
    long i = (long)blockIdx.x * blockDim.x + threadIdx.x;
    if (i >= (long)BB * CC * TDD) return;
    int  j  = (int)(i % TDD);
    long bc = i / TDD;
    int  c  = (int)(bc % CC);
    int  b  = (int)(bc / CC);
    int  p  = j >> 9;
    int  m  = j & 511;
    t[i] = x3[(long)b * MD + (long)m * DD + c * FF + p];
}

__global__ void build_out_k(const float* __restrict__ t2, float* __restrict__ out) {
    long i = (long)blockIdx.x * blockDim.x + threadIdx.x;
    if (i >= (long)BB * MD) return;
    int  d  = (int)(i % DD);
    long bm = i / DD;
    int  m  = (int)(bm % MM);
    int  b  = (int)(bm / MM);
    int  c  = d >> 3;
    int  p  = d & 7;
    out[i] = t2[(long)b * (CC * TDD) + (long)c * TDD + p * MM + m];
}

// ---------------- launch ----------------
extern "C" void kernel_launch(void* const* d_in, const int* in_sizes, int n_in,
                              void* d_out, int out_size) {
    const float* x     = (const float*)d_in[0];
    const float* scale = (const float*)d_in[1];
    const float* wq    = (const float*)d_in[2];
    const float* wk    = (const float*)d_in[3];
    const float* wv    = (const float*)d_in[4];
    const float* lin_w = (const float*)d_in[5];
    const float* lin_b = (const float*)d_in[6];
    const float* twq   = (const float*)d_in[7];
    const float* twk   = (const float*)d_in[8];
    const float* twv   = (const float*)d_in[9];
    float* out = (float*)d_out;

    float *x1, *q, *k, *v, *s, *cat, *x2, *x3, *t, *tq, *tk, *tv, *s2, *s2p, *t2, *ff;
    float *rwq, *rwk, *rwv, *rlw, *rtwq, *rtwk, *rtwv;
    cudaGetSymbolAddress((void**)&x1,  g_x1);
    cudaGetSymbolAddress((void**)&q,   g_q);
    cudaGetSymbolAddress((void**)&k,   g_k);
    cudaGetSymbolAddress((void**)&v,   g_v);
    cudaGetSymbolAddress((void**)&s,   g_s);
    cudaGetSymbolAddress((void**)&cat, g_cat);
    cudaGetSymbolAddress((void**)&x2,  g_x2);
    cudaGetSymbolAddress((void**)&x3,  g_x3);
    cudaGetSymbolAddress((void**)&t,   g_t);
    cudaGetSymbolAddress((void**)&tq,  g_tq);
    cudaGetSymbolAddress((void**)&tk,  g_tk);
    cudaGetSymbolAddress((void**)&tv,  g_tv);
    cudaGetSymbolAddress((void**)&s2,  g_s2);
    cudaGetSymbolAddress((void**)&s2p, g_s2p);
    cudaGetSymbolAddress((void**)&t2,  g_t2);
    cudaGetSymbolAddress((void**)&ff,  g_ff);
    cudaGetSymbolAddress((void**)&rwq, g_rwq);
    cudaGetSymbolAddress((void**)&rwk, g_rwk);
    cudaGetSymbolAddress((void**)&rwv, g_rwv);
    cudaGetSymbolAddress((void**)&rlw, g_rlw);
    cudaGetSymbolAddress((void**)&rtwq, g_rtwq);
    cudaGetSymbolAddress((void**)&rtwk, g_rtwk);
    cudaGetSymbolAddress((void**)&rtwv, g_rtwv);

    cudaFuncSetAttribute(tg_k<false,false,false,true >, cudaFuncAttributeMaxDynamicSharedMemorySize, TG_SMEM);
    cudaFuncSetAttribute(tg_k<true, false,false,false>, cudaFuncAttributeMaxDynamicSharedMemorySize, TG_SMEM);
    cudaFuncSetAttribute(tg_k<false,true, true, false>, cudaFuncAttributeMaxDynamicSharedMemorySize, TG_SMEM);
    cudaFuncSetAttribute(tg_k<false,false,false,false>, cudaFuncAttributeMaxDynamicSharedMemorySize, TG_SMEM);

    const float th1 = -2.0f * log2f(10000.0f) / (float)DD;
    const float th2 = -2.0f * log2f(10000.0f) / (float)TDD;
    const float al1 = 1.0f / sqrtf((float)DD);
    const float al2 = 1.0f / sqrtf((float)TDD);

    // 0) tf32-round weights into scratch
    roundw_k<<<2048, 256>>>(wq, rwq, (long)HH * DD * DD);
    roundw_k<<<2048, 256>>>(wk, rwk, (long)HH * DD * DD);
    roundw_k<<<2048, 256>>>(wv, rwv, (long)HH * DD * DD);
    roundw_k<<<2048, 256>>>(lin_w, rlw, (long)HH * DD * DD);
    roundw_k<<<4096, 256>>>(twq, rtwq, (long)TDD * TDD);
    roundw_k<<<4096, 256>>>(twk, rtwk, (long)TDD * TDD);
    roundw_k<<<4096, 256>>>(twv, rtwv, (long)TDD * TDD);

    // 1) x1 = rmsnorm(x)  (tf32-rounded)
    rms_reduce_k<<<BB, 1024>>>(x, ff);
    rms_apply_k<<<(BB * MD) / 256, 256>>>(x, scale, ff, x1);

    // 2) q/k/v[h,b] = x1[b] @ w[h]   (NN, rounded out)
    {
        dim3 g(DD / 128, MM / 128, HH * BB);
        tg_k<false,false,false,true><<<g, 256, TG_SMEM>>>(x1, DD, 0, MD, rwq, DD, (long)MD, 0,
                                                          q, DD, (long)BB * MD, MD,
                                                          nullptr, 0, 0, nullptr, DD, BB, 1.f);
        tg_k<false,false,false,true><<<g, 256, TG_SMEM>>>(x1, DD, 0, MD, rwk, DD, (long)MD, 0,
                                                          k, DD, (long)BB * MD, MD,
                                                          nullptr, 0, 0, nullptr, DD, BB, 1.f);
        tg_k<false,false,false,true><<<g, 256, TG_SMEM>>>(x1, DD, 0, MD, rwv, DD, (long)MD, 0,
                                                          v, DD, (long)BB * MD, MD,
                                                          nullptr, 0, 0, nullptr, DD, BB, 1.f);
    }

    // 3) RoPE on q,k  (rounded out)
    {
        long tp = (long)HH * BB * MM * (DD / 2);
        int blocks = (int)((tp + 255) / 256);
        rope_k<<<blocks, 256>>>(q, tp, DD / 2, MM, th1, 1);
        rope_k<<<blocks, 256>>>(k, tp, DD / 2, MM, th1, 1);
    }

    // 4) S = (q@k^T)/sqrt(D) (TRANSB); softmax (rounded); O = P @ v (NN, rounded, cat layout)
    {
        dim3 g(MM / 128, MM / 128, HH * BB);
        tg_k<true,false,false,false><<<g, 256, TG_SMEM>>>(q, DD, (long)BB * MD, MD,
                                                          k, DD, (long)BB * MD, MD,
                                                          s, MM, (long)BB * MM * MM, (long)MM * MM,
                                                          nullptr, 0, 0, nullptr, DD, BB, al1);
        long nrows = (long)HH * BB * MM;
        softmax_k<<<(int)(nrows / 8), 256>>>(s, MM, nrows, 1);
        dim3 g2(DD / 128, MM / 128, HH * BB);
        tg_k<false,false,false,true><<<g2, 256, TG_SMEM>>>(s, MM, (long)BB * MM * MM, (long)MM * MM,
                                                           v, DD, (long)BB * MD, MD,
                                                           cat, HH * DD, (long)DD, (long)MM * HH * DD,
                                                           nullptr, 0, 0, nullptr, MM, BB, 1.f);
    }

    // 5) x2 = x1 + cat @ lin_w + lin_b   (no round; feeds rmsnorm only)
    {
        dim3 g(DD / 128, (BB * MM) / 128, 1);
        tg_k<false,true,true,false><<<g, 256, TG_SMEM>>>(cat, HH * DD, 0, 0, rlw, DD, 0, 0,
                                                         x2, DD, 0, 0,
                                                         x1, DD, 0, lin_b, HH * DD, 1, 1.f);
    }

    // 6) x3 = rmsnorm(x2)  (rounded)
    rms_reduce_k<<<BB, 1024>>>(x2, ff);
    rms_apply_k<<<(BB * MD) / 256, 256>>>(x2, scale, ff, x3);

    // 7) t  (channel transpose of rounded x3)
    build_t_k<<<(int)(((long)BB * CC * TDD) / 256), 256>>>(x3, t);

    // 8) tq/tk/tv = t @ tw   (M=2048, N=4096, K=4096; feed fp32 stage-2, no round)
    {
        dim3 g(TDD / 128, (BB * CC) / 128, 1);
        tg_k<false,false,false,false><<<g, 256, TG_SMEM>>>(t, TDD, 0, 0, rtwq, TDD, 0, 0, tq, TDD, 0, 0,
                                                           nullptr, 0, 0, nullptr, TDD, 1, 1.f);
        tg_k<false,false,false,false><<<g, 256, TG_SMEM>>>(t, TDD, 0, 0, rtwk, TDD, 0, 0, tk, TDD, 0, 0,
                                                           nullptr, 0, 0, nullptr, TDD, 1, 1.f);
        tg_k<false,false,false,false><<<g, 256, TG_SMEM>>>(t, TDD, 0, 0, rtwv, TDD, 0, 0, tv, TDD, 0, 0,
                                                           nullptr, 0, 0, nullptr, TDD, 1, 1.f);
    }

    // 9) RoPE on tq,tk (fp32, no round)
    {
        long tp = (long)BB * CC * (TDD / 2);
        int blocks = (int)((tp + 255) / 256);
        rope_k<<<blocks, 256>>>(tq, tp, TDD / 2, CC, th2, 0);
        rope_k<<<blocks, 256>>>(tk, tp, TDD / 2, CC, th2, 0);
    }

    // 10) S2 = (tq @ tk^T)/64 via split-K 8; reduce; softmax; t2 = t + P2 @ tv
    {
        dim3 g(1, 1, 8 * BB);       // zo = K-split index, zi = batch
        sgemm_k<true,false,false><<<g, 256>>>(tq, TDD, 512, (long)CC * TDD,
                                              tk, TDD, 512, (long)CC * TDD,
                                              s2p, CC, (long)BB * CC * CC, (long)CC * CC,
                                              nullptr, 0, 0, nullptr, 512, BB, al2);
        s2red_k<<<(BB * CC * CC + 255) / 256, 256>>>(s2p, s2);
        softmax_k<<<(BB * CC) / 8, 256>>>(s2, CC, (long)BB * CC, 0);
        dim3 g2(TDD / 64, 1, BB);
        sgemm_k<false,true,false><<<g2, 256>>>(s2, CC, 0, (long)CC * CC,
                                               tv, TDD, 0, (long)CC * TDD,
                                               t2, TDD, 0, (long)CC * TDD,
                                               t, TDD, (long)CC * TDD, nullptr,
                                               CC, BB, 1.f);
    }

    // 11) inverse transpose into d_out
    build_out_k<<<(int)(((long)BB * MD) / 256), 256>>>(t2, out);
}